// round 2
// baseline (speedup 1.0000x reference)
#include <cuda_runtime.h>
#include <cstdint>

#define QN   10000
#define NCAM 6
#define DIM  256
#define HWF  2816     // 32*88
#define NH   8
#define HD   32
#define HFv  32
#define WFv  88
#define MROWS (NCAM*QN)   // 60000
#define OAC  192          // 128 offsets + 64 attn logits

// ---------------- scratch (static device globals; no allocations) ----------------
__device__ float d_value[NCAM*NH*HWF*HD];   // (cam, head, hw, hd)
__device__ float d_offattn[(size_t)MROWS*OAC];
__device__ float d_S[(size_t)QN*DIM];       // camera-reduced, /count applied
__device__ float d_gflag[QN];
__device__ float d_bias2[NCAM*DIM];
__device__ float d_Wc[DIM*DIM];             // W_out @ W_inner
__device__ float d_bi2[DIM];                // W_out @ b_inner
__device__ int   d_mask_mode;               // 0=u8, 1=i32, 2=f32

// ---------------- mask dtype detection ----------------
__global__ void detect_mask(const unsigned int* __restrict__ m) {
    bool sawF = false, sawMulti = false;
    for (int i = 0; i < 256; i++) {
        unsigned int w = m[i];
        if (w == 0x3F800000u) sawF = true;
        else if (w > 1u) sawMulti = true;
    }
    d_mask_mode = sawF ? 2 : (sawMulti ? 0 : 1);
}

__device__ __forceinline__ int mask_elem(const void* mask, size_t idx, int mode) {
    if (mode == 0) return ((const unsigned char*)mask)[idx] != 0;
    if (mode == 1) return ((const int*)mask)[idx] != 0;
    return ((const float*)mask)[idx] != 0.f;
}

// ---------------- tiny precompute kernels ----------------
__global__ void prep_bias2(const float* __restrict__ lvl, const float* __restrict__ camemb,
                           const float* __restrict__ Wv, const float* __restrict__ bv) {
    int c = blockIdx.x, j = threadIdx.x;
    __shared__ float e[DIM];
    e[j] = lvl[j] + camemb[c*DIM + j];
    __syncthreads();
    const float4* w4 = (const float4*)(Wv + (size_t)j*DIM);
    const float4* e4 = (const float4*)e;
    float s = bv[j];
    #pragma unroll 8
    for (int k = 0; k < DIM/4; k++) {
        float4 w = w4[k]; float4 ev = e4[k];
        s += w.x*ev.x + w.y*ev.y + w.z*ev.z + w.w*ev.w;
    }
    d_bias2[c*DIM + j] = s;
}

__global__ void prep_wc(const float* __restrict__ Wo, const float* __restrict__ Wi) {
    int i = blockIdx.x, j = threadIdx.x;
    __shared__ float wo[DIM];
    wo[j] = Wo[(size_t)i*DIM + j];
    __syncthreads();
    float s = 0.f;
    #pragma unroll 8
    for (int k = 0; k < DIM; k++) s += wo[k] * Wi[(size_t)k*DIM + j];
    d_Wc[(size_t)i*DIM + j] = s;
}

__global__ void prep_bi2(const float* __restrict__ Wo, const float* __restrict__ bi) {
    int i = threadIdx.x;
    float s = 0.f;
    #pragma unroll 8
    for (int k = 0; k < DIM; k++) s += Wo[(size_t)i*DIM + k] * bi[k];
    d_bi2[i] = s;
}

// ---------------- GEMM 1: value = features^T @ W_value^T + bias2 ----------------
__global__ __launch_bounds__(256) void gemm_value(const float* __restrict__ feat,
                                                  const float* __restrict__ Wv) {
    __shared__ float As[16][128];
    __shared__ float Bs[16][64];
    const int tid = threadIdx.x;
    const int bm = blockIdx.y, bn = blockIdx.x;
    const int camI = (bm*128)/HWF;
    const int p0   = (bm*128)%HWF;
    const int j0   = bn*64;
    const int ty = tid>>4, tx = tid&15;
    const int akk = tid>>4, apg = tid&15;
    const int bjj = tid>>2, bkq = tid&3;
    const float* fb = feat + (size_t)camI*DIM*HWF + p0;
    float acc[8][4] = {};
    for (int k0 = 0; k0 < DIM; k0 += 16) {
        float4 a0 = *(const float4*)(fb + (size_t)(k0+akk)*HWF + apg*8);
        float4 a1 = *(const float4*)(fb + (size_t)(k0+akk)*HWF + apg*8 + 4);
        float4 b  = *(const float4*)(Wv + (size_t)(j0+bjj)*DIM + k0 + bkq*4);
        *(float4*)&As[akk][apg*8]   = a0;
        *(float4*)&As[akk][apg*8+4] = a1;
        Bs[bkq*4+0][bjj]=b.x; Bs[bkq*4+1][bjj]=b.y; Bs[bkq*4+2][bjj]=b.z; Bs[bkq*4+3][bjj]=b.w;
        __syncthreads();
        #pragma unroll
        for (int k = 0; k < 16; k++) {
            float4 a0r = *(float4*)&As[k][ty*8];
            float4 a1r = *(float4*)&As[k][ty*8+4];
            float4 br  = *(float4*)&Bs[k][tx*4];
            float ar[8] = {a0r.x,a0r.y,a0r.z,a0r.w,a1r.x,a1r.y,a1r.z,a1r.w};
            float bb[4] = {br.x,br.y,br.z,br.w};
            #pragma unroll
            for (int i = 0; i < 8; i++)
                #pragma unroll
                for (int j = 0; j < 4; j++) acc[i][j] += ar[i]*bb[j];
        }
        __syncthreads();
    }
    const int jbase = j0 + tx*4;
    const int h = jbase >> 5, jm = jbase & 31;
    float4 b2 = *(const float4*)&d_bias2[camI*DIM + jbase];
    float* vout = d_value + (size_t)(camI*NH + h)*HWF*HD + jm;
    #pragma unroll
    for (int i = 0; i < 8; i++) {
        int p = p0 + ty*8 + i;
        float4 o = make_float4(acc[i][0]+b2.x, acc[i][1]+b2.y, acc[i][2]+b2.z, acc[i][3]+b2.w);
        *(float4*)(vout + (size_t)p*HD) = o;
    }
}

// ---------------- GEMM 2: offattn = (queries+pos) @ [W_off;W_attn]^T + bias ----------------
__global__ __launch_bounds__(256) void gemm_offattn(const float* __restrict__ qry,
                                                    const float* __restrict__ pos,
                                                    const float* __restrict__ Woff,
                                                    const float* __restrict__ boff,
                                                    const float* __restrict__ Wattn,
                                                    const float* __restrict__ battn) {
    __shared__ float As[16][128];
    __shared__ float Bs[16][64];
    const int tid = threadIdx.x;
    const int m0 = blockIdx.y*128;
    const int j0 = blockIdx.x*64;
    const int ty = tid>>4, tx = tid&15;
    const int arr = tid>>1, ah = tid&1;
    const int bjj = tid>>2, bkq = tid&3;
    const int jg = j0 + bjj;
    const float* wrow = (jg < 128) ? (Woff + (size_t)jg*DIM) : (Wattn + (size_t)(jg-128)*DIM);
    float acc[8][4] = {};
    for (int k0 = 0; k0 < DIM; k0 += 16) {
        int m = m0 + arr;
        float4 a0 = make_float4(0,0,0,0), a1 = a0;
        if (m < MROWS) {
            const float4* q4 = (const float4*)(qry + (size_t)m*DIM + k0 + ah*8);
            const float4* p4 = (const float4*)(pos + (size_t)m*DIM + k0 + ah*8);
            float4 qa = q4[0], qb = q4[1], pa = p4[0], pb = p4[1];
            a0 = make_float4(qa.x+pa.x, qa.y+pa.y, qa.z+pa.z, qa.w+pa.w);
            a1 = make_float4(qb.x+pb.x, qb.y+pb.y, qb.z+pb.z, qb.w+pb.w);
        }
        float4 b = *(const float4*)(wrow + k0 + bkq*4);
        As[ah*8+0][arr]=a0.x; As[ah*8+1][arr]=a0.y; As[ah*8+2][arr]=a0.z; As[ah*8+3][arr]=a0.w;
        As[ah*8+4][arr]=a1.x; As[ah*8+5][arr]=a1.y; As[ah*8+6][arr]=a1.z; As[ah*8+7][arr]=a1.w;
        Bs[bkq*4+0][bjj]=b.x; Bs[bkq*4+1][bjj]=b.y; Bs[bkq*4+2][bjj]=b.z; Bs[bkq*4+3][bjj]=b.w;
        __syncthreads();
        #pragma unroll
        for (int k = 0; k < 16; k++) {
            float4 a0r = *(float4*)&As[k][ty*8];
            float4 a1r = *(float4*)&As[k][ty*8+4];
            float4 br  = *(float4*)&Bs[k][tx*4];
            float ar[8] = {a0r.x,a0r.y,a0r.z,a0r.w,a1r.x,a1r.y,a1r.z,a1r.w};
            float bb[4] = {br.x,br.y,br.z,br.w};
            #pragma unroll
            for (int i = 0; i < 8; i++)
                #pragma unroll
                for (int j = 0; j < 4; j++) acc[i][j] += ar[i]*bb[j];
        }
        __syncthreads();
    }
    const int jbase = j0 + tx*4;
    float4 bias = (jbase < 128) ? *(const float4*)&boff[jbase]
                                : *(const float4*)&battn[jbase-128];
    #pragma unroll
    for (int i = 0; i < 8; i++) {
        int m = m0 + ty*8 + i;
        if (m < MROWS) {
            float4 o = make_float4(acc[i][0]+bias.x, acc[i][1]+bias.y,
                                   acc[i][2]+bias.z, acc[i][3]+bias.w);
            *(float4*)&d_offattn[(size_t)m*OAC + jbase] = o;
        }
    }
}

// ---------------- sampling + softmax + camera reduction ----------------
__global__ __launch_bounds__(256) void sample_kernel(const float* __restrict__ ref,
                                                     const void* __restrict__ mask) {
    const int q = blockIdx.x;
    const int tid = threadIdx.x;
    const int h = tid>>5, l = tid&31;
    const int corner = l>>3, c8 = l&7;
    const int ox = corner&1, oy = corner>>1;
    __shared__ float s_hit[NCAM];
    __shared__ float s_inv, s_g;
    if (tid < NCAM) {
        const int mode = d_mask_mode;
        size_t base = (size_t)(tid*QN + q)*8;   // (n,q,ZANCH,2) elements
        int hit = mask_elem(mask, base+0, mode) | mask_elem(mask, base+2, mode) |
                  mask_elem(mask, base+4, mode) | mask_elem(mask, base+6, mode);
        s_hit[tid] = hit ? 1.f : 0.f;
    }
    __syncthreads();
    if (tid == 0) {
        float c = s_hit[0]+s_hit[1]+s_hit[2]+s_hit[3]+s_hit[4]+s_hit[5];
        s_g = (c > 0.f) ? 1.f : 0.f;
        s_inv = 1.f / fmaxf(c, 1.f);
    }
    __syncthreads();
    float ax=0.f, ay=0.f, az=0.f, aw=0.f;
    for (int camI = 0; camI < NCAM; camI++) {
        if (s_hit[camI] == 0.f) continue;
        const float* row = d_offattn + (size_t)(camI*QN + q)*OAC;
        float logit = row[128 + h*8 + c8];
        float ofx   = row[h*16 + c8*2];
        float ofy   = row[h*16 + c8*2 + 1];
        const float* rp = ref + ((size_t)(camI*QN + q)*4 + (c8&3))*2;
        float rx = rp[0], ry = rp[1];
        float mx = logit;
        mx = fmaxf(mx, __shfl_xor_sync(0xffffffffu, mx, 1, 8));
        mx = fmaxf(mx, __shfl_xor_sync(0xffffffffu, mx, 2, 8));
        mx = fmaxf(mx, __shfl_xor_sync(0xffffffffu, mx, 4, 8));
        float e = __expf(logit - mx);
        float sm = e;
        sm += __shfl_xor_sync(0xffffffffu, sm, 1, 8);
        sm += __shfl_xor_sync(0xffffffffu, sm, 2, 8);
        sm += __shfl_xor_sync(0xffffffffu, sm, 4, 8);
        float w = e / sm;
        const float* vb = d_value + (size_t)(camI*NH + h)*HWF*HD + c8*4;
        #pragma unroll
        for (int p = 0; p < 8; p++) {
            float wp  = __shfl_sync(0xffffffffu, w,   p, 8);
            float fx  = __shfl_sync(0xffffffffu, ofx, p, 8);
            float fy  = __shfl_sync(0xffffffffu, ofy, p, 8);
            float rxp = __shfl_sync(0xffffffffu, rx,  p, 8);
            float ryp = __shfl_sync(0xffffffffu, ry,  p, 8);
            float x = fmaf(rxp, (float)WFv, fx) - 0.5f;
            float y = fmaf(ryp, (float)HFv, fy) - 0.5f;
            float xf = floorf(x), yf = floorf(y);
            float dx = x - xf, dy = y - yf;
            int xi = (int)xf + ox;
            int yi = (int)yf + oy;
            float wx = ox ? dx : (1.f - dx);
            float wy = oy ? dy : (1.f - dy);
            bool valid = (xi >= 0) && (xi < WFv) && (yi >= 0) && (yi < HFv);
            float wc = valid ? (wp*wx*wy) : 0.f;
            int pix = min(max(yi,0),HFv-1)*WFv + min(max(xi,0),WFv-1);
            float4 v = *(const float4*)(vb + (size_t)pix*HD);
            ax = fmaf(wc, v.x, ax); ay = fmaf(wc, v.y, ay);
            az = fmaf(wc, v.z, az); aw = fmaf(wc, v.w, aw);
        }
    }
    ax += __shfl_xor_sync(0xffffffffu, ax, 8);  ax += __shfl_xor_sync(0xffffffffu, ax, 16);
    ay += __shfl_xor_sync(0xffffffffu, ay, 8);  ay += __shfl_xor_sync(0xffffffffu, ay, 16);
    az += __shfl_xor_sync(0xffffffffu, az, 8);  az += __shfl_xor_sync(0xffffffffu, az, 16);
    aw += __shfl_xor_sync(0xffffffffu, aw, 8);  aw += __shfl_xor_sync(0xffffffffu, aw, 16);
    if (l < 8) {
        float inv = s_inv;
        float4 o = make_float4(ax*inv, ay*inv, az*inv, aw*inv);
        *(float4*)&d_S[(size_t)q*DIM + h*HD + c8*4] = o;
    }
    if (tid == 0) d_gflag[q] = s_g;
}

// ---------------- GEMM 3: out = S @ Wc^T + b_out + g*bi2 ----------------
__global__ __launch_bounds__(256) void gemm_final(const float* __restrict__ bout,
                                                  float* __restrict__ out) {
    __shared__ float As[16][128];
    __shared__ float Bs[16][64];
    const int tid = threadIdx.x;
    const int m0 = blockIdx.y*128;
    const int j0 = blockIdx.x*64;
    const int ty = tid>>4, tx = tid&15;
    const int arr = tid>>1, ah = tid&1;
    const int bjj = tid>>2, bkq = tid&3;
    float acc[8][4] = {};
    for (int k0 = 0; k0 < DIM; k0 += 16) {
        int m = m0 + arr;
        float4 a0 = make_float4(0,0,0,0), a1 = a0;
        if (m < QN) {
            const float4* s4 = (const float4*)(d_S + (size_t)m*DIM + k0 + ah*8);
            a0 = s4[0]; a1 = s4[1];
        }
        float4 b = *(const float4*)(d_Wc + (size_t)(j0+bjj)*DIM + k0 + bkq*4);
        As[ah*8+0][arr]=a0.x; As[ah*8+1][arr]=a0.y; As[ah*8+2][arr]=a0.z; As[ah*8+3][arr]=a0.w;
        As[ah*8+4][arr]=a1.x; As[ah*8+5][arr]=a1.y; As[ah*8+6][arr]=a1.z; As[ah*8+7][arr]=a1.w;
        Bs[bkq*4+0][bjj]=b.x; Bs[bkq*4+1][bjj]=b.y; Bs[bkq*4+2][bjj]=b.z; Bs[bkq*4+3][bjj]=b.w;
        __syncthreads();
        #pragma unroll
        for (int k = 0; k < 16; k++) {
            float4 a0r = *(float4*)&As[k][ty*8];
            float4 a1r = *(float4*)&As[k][ty*8+4];
            float4 br  = *(float4*)&Bs[k][tx*4];
            float ar[8] = {a0r.x,a0r.y,a0r.z,a0r.w,a1r.x,a1r.y,a1r.z,a1r.w};
            float bb[4] = {br.x,br.y,br.z,br.w};
            #pragma unroll
            for (int i = 0; i < 8; i++)
                #pragma unroll
                for (int j = 0; j < 4; j++) acc[i][j] += ar[i]*bb[j];
        }
        __syncthreads();
    }
    const int jbase = j0 + tx*4;
    float4 bo  = *(const float4*)&bout[jbase];
    float4 bi2 = *(const float4*)&d_bi2[jbase];
    #pragma unroll
    for (int i = 0; i < 8; i++) {
        int m = m0 + ty*8 + i;
        if (m < QN) {
            float g = d_gflag[m];
            float4 o = make_float4(acc[i][0]+bo.x+g*bi2.x, acc[i][1]+bo.y+g*bi2.y,
                                   acc[i][2]+bo.z+g*bi2.z, acc[i][3]+bo.w+g*bi2.w);
            *(float4*)&out[(size_t)m*DIM + jbase] = o;
        }
    }
}

// ---------------- launch ----------------
extern "C" void kernel_launch(void* const* d_in, const int* in_sizes, int n_in,
                              void* d_out, int out_size) {
    const float* queries = (const float*)d_in[0];
    const float* pos     = (const float*)d_in[1];
    const float* lvl     = (const float*)d_in[2];
    const float* camemb  = (const float*)d_in[3];
    const float* feat    = (const float*)d_in[4];
    const float* ref     = (const float*)d_in[5];
    const void*  mask    = (const void*)d_in[6];
    const float* W_value = (const float*)d_in[7];
    const float* b_value = (const float*)d_in[8];
    const float* W_off   = (const float*)d_in[9];
    const float* b_off   = (const float*)d_in[10];
    const float* W_attn  = (const float*)d_in[11];
    const float* b_attn  = (const float*)d_in[12];
    const float* W_inner = (const float*)d_in[13];
    const float* b_inner = (const float*)d_in[14];
    const float* W_out   = (const float*)d_in[15];
    const float* b_out   = (const float*)d_in[16];
    float* out = (float*)d_out;

    detect_mask<<<1, 1>>>((const unsigned int*)mask);
    prep_bias2<<<NCAM, DIM>>>(lvl, camemb, W_value, b_value);
    prep_wc<<<DIM, DIM>>>(W_out, W_inner);
    prep_bi2<<<1, DIM>>>(W_out, b_inner);
    gemm_value<<<dim3(4, 132), 256>>>(feat, W_value);
    gemm_offattn<<<dim3(3, 469), 256>>>(queries, pos, W_off, b_off, W_attn, b_attn);
    sample_kernel<<<QN, 256>>>(ref, mask);
    gemm_final<<<dim3(4, 79), 256>>>(b_out, out);
    (void)in_sizes; (void)n_in; (void)out_size;
}